// round 1
// baseline (speedup 1.0000x reference)
#include <cuda_runtime.h>
#include <cuda_bf16.h>
#include <math.h>

// ---------------- Problem constants ----------------
#define DIMN   1024
#define QK     128        // q/k total width
#define EXPN   2048
#define HEADS  8
#define DQK    16         // per-head qk dim
#define DV     128        // per-head v dim
#define BATCH  16
#define SEQ    1024
#define ROWS   (BATCH*SEQ)        // 16384
#define ECOLS  (2*QK + 2*EXPN)    // 4352
#define OUTC   2048               // concat width

// ---------------- Scratch (static device globals; no allocation) ----------------
__device__ float g_xn[(size_t)ROWS * DIMN];       //  64 MB
__device__ float g_h [(size_t)ROWS * ECOLS];      // 285 MB
__device__ float g_go[(size_t)ROWS * OUTC];       // 134 MB  (cols [0,1024)=geglu_local, [1024,2048)=attn)
__device__ float g_v [(size_t)ROWS * DIMN];       //  64 MB  (attn value = geglu[...,1024:2048])

// ---------------- LayerNorm ----------------
__global__ __launch_bounds__(256) void ln_kernel(const float* __restrict__ x,
                                                 const float* __restrict__ w,
                                                 float* __restrict__ out)
{
    const int row = blockIdx.x;
    const int t   = threadIdx.x;
    const float4* xr = (const float4*)(x + (size_t)row * DIMN);
    float4 xv = xr[t];

    __shared__ float red[8];
    // mean
    float s = xv.x + xv.y + xv.z + xv.w;
    #pragma unroll
    for (int o = 16; o; o >>= 1) s += __shfl_xor_sync(0xffffffffu, s, o);
    if ((t & 31) == 0) red[t >> 5] = s;
    __syncthreads();
    float mean = 0.f;
    #pragma unroll
    for (int i = 0; i < 8; i++) mean += red[i];
    mean *= (1.0f / DIMN);
    __syncthreads();
    // var
    float dx0 = xv.x - mean, dx1 = xv.y - mean, dx2 = xv.z - mean, dx3 = xv.w - mean;
    float vs = dx0*dx0 + dx1*dx1 + dx2*dx2 + dx3*dx3;
    #pragma unroll
    for (int o = 16; o; o >>= 1) vs += __shfl_xor_sync(0xffffffffu, vs, o);
    if ((t & 31) == 0) red[t >> 5] = vs;
    __syncthreads();
    float var = 0.f;
    #pragma unroll
    for (int i = 0; i < 8; i++) var += red[i];
    var *= (1.0f / DIMN);
    const float inv = rsqrtf(var + 1e-5f);

    const float4 wv = ((const float4*)w)[t];
    float4 o4;
    o4.x = dx0 * inv * wv.x;
    o4.y = dx1 * inv * wv.y;
    o4.z = dx2 * inv * wv.z;
    o4.w = dx3 * inv * wv.w;
    ((float4*)(out + (size_t)row * DIMN))[t] = o4;
}

// ---------------- SGEMM  C[m,n] = sum_k A[m,k]*B[n,k] (+resid) ----------------
// A: MxK row-major, B: NxK row-major (both K-contiguous -> "NT")
#define BM 128
#define BN 128
#define BK 16
__global__ __launch_bounds__(256) void sgemm_nt(const float* __restrict__ A,
                                                const float* __restrict__ Bm,
                                                const float* __restrict__ resid,
                                                float* __restrict__ C,
                                                int M, int N, int K)
{
    __shared__ __align__(16) float As[BK][BM];
    __shared__ __align__(16) float Bs[BK][BN];

    const int tid = threadIdx.x;
    const int bm  = blockIdx.y * BM;
    const int bn  = blockIdx.x * BN;
    const int tx  = tid & 15;   // n
    const int ty  = tid >> 4;   // m

    float acc[8][8];
    #pragma unroll
    for (int i = 0; i < 8; i++)
        #pragma unroll
        for (int j = 0; j < 8; j++) acc[i][j] = 0.f;

    for (int k0 = 0; k0 < K; k0 += BK) {
        #pragma unroll
        for (int i = 0; i < 2; i++) {
            int li  = tid + i * 256;        // 0..511 float4 slots
            int row = li >> 2;              // 0..127
            int col = (li & 3) * 4;         // 0,4,8,12
            float4 av = *(const float4*)(A  + (size_t)(bm + row) * K + k0 + col);
            As[col+0][row] = av.x; As[col+1][row] = av.y;
            As[col+2][row] = av.z; As[col+3][row] = av.w;
            float4 bv = *(const float4*)(Bm + (size_t)(bn + row) * K + k0 + col);
            Bs[col+0][row] = bv.x; Bs[col+1][row] = bv.y;
            Bs[col+2][row] = bv.z; Bs[col+3][row] = bv.w;
        }
        __syncthreads();
        #pragma unroll
        for (int k = 0; k < BK; k++) {
            float4 a0 = *(const float4*)&As[k][ty*8];
            float4 a1 = *(const float4*)&As[k][ty*8 + 4];
            float4 b0 = *(const float4*)&Bs[k][tx*8];
            float4 b1 = *(const float4*)&Bs[k][tx*8 + 4];
            float ar[8] = {a0.x,a0.y,a0.z,a0.w,a1.x,a1.y,a1.z,a1.w};
            float br[8] = {b0.x,b0.y,b0.z,b0.w,b1.x,b1.y,b1.z,b1.w};
            #pragma unroll
            for (int i = 0; i < 8; i++)
                #pragma unroll
                for (int j = 0; j < 8; j++)
                    acc[i][j] = fmaf(ar[i], br[j], acc[i][j]);
        }
        __syncthreads();
    }

    #pragma unroll
    for (int i = 0; i < 8; i++) {
        int m = bm + ty*8 + i;
        #pragma unroll
        for (int j = 0; j < 8; j += 4) {
            int n = bn + tx*8 + j;
            float4 v = make_float4(acc[i][j], acc[i][j+1], acc[i][j+2], acc[i][j+3]);
            if (resid) {
                float4 r = *(const float4*)(resid + (size_t)m * N + n);
                v.x += r.x; v.y += r.y; v.z += r.z; v.w += r.w;
            }
            *(float4*)(C + (size_t)m * N + n) = v;
        }
    }
}

// ---------------- GeGLU (exact gelu) ----------------
__device__ __forceinline__ float gelu_exact(float x) {
    return 0.5f * x * (1.0f + erff(x * 0.70710678118654752f));
}
__global__ __launch_bounds__(256) void geglu_kernel()
{
    size_t idx = (size_t)blockIdx.x * blockDim.x + threadIdx.x;   // over ROWS*2048
    size_t r = idx >> 11;           // /2048
    int    e = (int)(idx & 2047);
    const float* hr = g_h + r * ECOLS;
    float lin = hr[256 + e];
    float pg  = hr[2304 + e];
    float g = lin * gelu_exact(pg);
    if (e < 1024) g_go[r * OUTC + e] = g;
    else          g_v [r * DIMN + (e - 1024)] = g;
}

// ---------------- Attention (flash-style, causal + softplus(pbm)*(j-i) bias) ----------------
#define BQ  64
#define BKT 32
__global__ __launch_bounds__(256) void attn_kernel(const float* __restrict__ pbm_ptr)
{
    const int qb = blockIdx.x;          // 0..15
    const int bh = blockIdx.y;          // 0..127
    const int b  = bh >> 3, hd = bh & 7;
    const int q0 = qb * BQ;
    float pbm = *pbm_ptr;
    const float sp = (pbm > 20.f) ? pbm : log1pf(expf(pbm));
    const float scale = 0.25f;          // 1/sqrt(16)

    __shared__ __align__(16) float Qs[BQ][DQK];
    __shared__ __align__(16) float Ks[BKT][DQK];
    __shared__ __align__(16) float Vs[BKT][DV];
    __shared__ float Ps[BQ][BKT];

    const int tid  = threadIdx.x;
    const int warp = tid >> 5, lane = tid & 31;
    const size_t base = (size_t)b * SEQ;

    // Load Q tile: 64x16 floats = 256 float4
    {
        int r = tid >> 2, c4 = (tid & 3) * 4;
        float4 qv = *(const float4*)(g_h + (base + q0 + r) * ECOLS + hd*DQK + c4);
        Qs[r][c4] = qv.x; Qs[r][c4+1] = qv.y; Qs[r][c4+2] = qv.z; Qs[r][c4+3] = qv.w;
    }

    float acc[8][4];
    float mrow[8], lrow[8];
    #pragma unroll
    for (int i = 0; i < 8; i++) {
        mrow[i] = -INFINITY; lrow[i] = 0.f;
        acc[i][0] = acc[i][1] = acc[i][2] = acc[i][3] = 0.f;
    }

    const int ktmax = (q0 + BQ - 1) / BKT;
    __syncthreads();

    for (int kt = 0; kt <= ktmax; kt++) {
        const int k0 = kt * BKT;
        if (tid < 128) {   // K tile: 32x16 = 128 float4
            int r = tid >> 2, c4 = (tid & 3) * 4;
            float4 kv = *(const float4*)(g_h + (base + k0 + r) * ECOLS + QK + hd*DQK + c4);
            Ks[r][c4] = kv.x; Ks[r][c4+1] = kv.y; Ks[r][c4+2] = kv.z; Ks[r][c4+3] = kv.w;
        }
        #pragma unroll
        for (int i = 0; i < 4; i++) {   // V tile: 32x128 = 1024 float4
            int li = tid + i * 256;
            int r  = li >> 5;
            int c4 = (li & 31) * 4;
            float4 vv = *(const float4*)(g_v + (base + k0 + r) * DIMN + hd*DV + c4);
            Vs[r][c4] = vv.x; Vs[r][c4+1] = vv.y; Vs[r][c4+2] = vv.z; Vs[r][c4+3] = vv.w;
        }
        __syncthreads();

        // scores: 64x32, 8 per thread
        #pragma unroll
        for (int i = 0; i < 8; i++) {
            int e = tid + i * 256;
            int q = e >> 5, j = e & 31;
            const float* qv = Qs[q];
            const float* kv = Ks[j];
            float s = 0.f;
            #pragma unroll
            for (int d = 0; d < DQK; d++) s = fmaf(qv[d], kv[d], s);
            int qi = q0 + q, kj = k0 + j;
            s = s * scale + ((kj <= qi) ? sp * (float)(kj - qi) : -INFINITY);
            Ps[q][j] = s;
        }
        __syncthreads();

        // online softmax: warp w owns queries w*8..w*8+7; lane = key index (BKT==32)
        #pragma unroll
        for (int i = 0; i < 8; i++) {
            int q = warp * 8 + i;
            float s = Ps[q][lane];
            float m = s;
            #pragma unroll
            for (int o = 16; o; o >>= 1) m = fmaxf(m, __shfl_xor_sync(0xffffffffu, m, o));
            float mn = fmaxf(mrow[i], m);
            float p  = __expf(s - mn);
            float ps = p;
            #pragma unroll
            for (int o = 16; o; o >>= 1) ps += __shfl_xor_sync(0xffffffffu, ps, o);
            float alpha = __expf(mrow[i] - mn);
            lrow[i] = lrow[i] * alpha + ps;
            mrow[i] = mn;
            Ps[q][lane] = p;
            #pragma unroll
            for (int d = 0; d < 4; d++) acc[i][d] *= alpha;
        }
        __syncwarp();

        // P @ V : lane owns dv = lane*4..lane*4+3
        #pragma unroll
        for (int i = 0; i < 8; i++) {
            int q = warp * 8 + i;
            #pragma unroll
            for (int j = 0; j < BKT; j++) {
                float p = Ps[q][j];
                float4 vv = *(const float4*)&Vs[j][lane * 4];
                acc[i][0] = fmaf(p, vv.x, acc[i][0]);
                acc[i][1] = fmaf(p, vv.y, acc[i][1]);
                acc[i][2] = fmaf(p, vv.z, acc[i][2]);
                acc[i][3] = fmaf(p, vv.w, acc[i][3]);
            }
        }
        __syncthreads();
    }

    #pragma unroll
    for (int i = 0; i < 8; i++) {
        int q = warp * 8 + i;
        float inv = 1.0f / lrow[i];
        float4 o = make_float4(acc[i][0]*inv, acc[i][1]*inv, acc[i][2]*inv, acc[i][3]*inv);
        *(float4*)(g_go + (base + q0 + q) * OUTC + 1024 + hd*DV + lane*4) = o;
    }
}

// ---------------- Launch ----------------
extern "C" void kernel_launch(void* const* d_in, const int* in_sizes, int n_in,
                              void* d_out, int out_size)
{
    const float* x       = (const float*)d_in[0];
    const float* norm_w  = (const float*)d_in[1];
    const float* expand  = (const float*)d_in[2];
    const float* project = (const float*)d_in[3];
    const float* pbm     = (const float*)d_in[4];
    float* out = (float*)d_out;

    float *p_xn, *p_h, *p_go;
    cudaGetSymbolAddress((void**)&p_xn, g_xn);
    cudaGetSymbolAddress((void**)&p_h,  g_h);
    cudaGetSymbolAddress((void**)&p_go, g_go);

    // 1) LayerNorm
    ln_kernel<<<ROWS, 256>>>(x, norm_w, p_xn);

    // 2) h = xn @ expand^T   (16384 x 4352 x 1024)
    {
        dim3 grid(ECOLS / BN, ROWS / BM);
        sgemm_nt<<<grid, 256>>>(p_xn, expand, nullptr, p_h, ROWS, ECOLS, DIMN);
    }

    // 3) GeGLU split
    {
        size_t total = (size_t)ROWS * 2048;
        geglu_kernel<<<(unsigned)(total / 256), 256>>>();
    }

    // 4) Attention
    {
        dim3 grid(SEQ / BQ, BATCH * HEADS);
        attn_kernel<<<grid, 256>>>(pbm);
    }

    // 5) y = go @ project^T + x   (16384 x 1024 x 2048)
    {
        dim3 grid(DIMN / BN, ROWS / BM);
        sgemm_nt<<<grid, 256>>>(p_go, project, x, out, ROWS, DIMN, OUTC);
    }
}

// round 3
// speedup vs baseline: 3.5480x; 3.5480x over previous
#include <cuda_runtime.h>
#include <cuda_bf16.h>
#include <math.h>
#include <stdint.h>

// ---------------- Problem constants ----------------
#define DIMN   1024
#define QKW    256        // q+k width
#define HEADS  8
#define DQK    16
#define DV     128
#define BATCH  16
#define SEQ    1024
#define ROWS   (BATCH*SEQ)     // 16384
#define ENROW  4352            // expand rows
#define GEGN   4096            // interleaved lin/pg columns
#define OUTC   2048

// ---------------- Scratch ----------------
__device__ __nv_bfloat16 g_xn[(size_t)ROWS * DIMN];     // 32MB  LN output
__device__ __nv_bfloat16 g_eb[(size_t)ENROW * DIMN];    // 8.9MB expand bf16 (reordered)
__device__ __nv_bfloat16 g_pb[(size_t)DIMN * OUTC];     // 4.2MB project bf16
__device__ float         g_qk[(size_t)ROWS * QKW];      // 16MB  q|k
__device__ float         g_v [(size_t)ROWS * DIMN];     // 64MB  attn value
__device__ __nv_bfloat16 g_go[(size_t)ROWS * OUTC];     // 64MB  concat(gl, attn) bf16

// ---------------- Weight conversion ----------------
// g_eb rows [0,4096): row 2e = expand[256+e] (linear), row 2e+1 = expand[2304+e] (pre_gelu)
// g_eb rows [4096,4352): expand[0..256) (q then k)
__global__ __launch_bounds__(256) void conv_expand(const float* __restrict__ src)
{
    int i  = blockIdx.x * 256 + threadIdx.x;     // float4 index over 4352*256
    int r  = i >> 8;
    int c4 = (i & 255) * 4;
    int srow = (r < GEGN) ? ((r & 1) ? 2304 + (r >> 1) : 256 + (r >> 1)) : (r - GEGN);
    float4 v = *(const float4*)(src + (size_t)srow * DIMN + c4);
    __nv_bfloat16* dst = g_eb + (size_t)r * DIMN + c4;
    *(__nv_bfloat162*)(dst)     = __floats2bfloat162_rn(v.x, v.y);
    *(__nv_bfloat162*)(dst + 2) = __floats2bfloat162_rn(v.z, v.w);
}
__global__ __launch_bounds__(256) void conv_project(const float* __restrict__ src)
{
    int i  = blockIdx.x * 256 + threadIdx.x;     // float4 index over 1024*512
    float4 v = *(const float4*)(src + (size_t)i * 4);
    __nv_bfloat16* dst = g_pb + (size_t)i * 4;
    *(__nv_bfloat162*)(dst)     = __floats2bfloat162_rn(v.x, v.y);
    *(__nv_bfloat162*)(dst + 2) = __floats2bfloat162_rn(v.z, v.w);
}

// ---------------- LayerNorm -> bf16 ----------------
__global__ __launch_bounds__(256) void ln_kernel(const float* __restrict__ x,
                                                 const float* __restrict__ w)
{
    const int row = blockIdx.x;
    const int t   = threadIdx.x;
    float4 xv = ((const float4*)(x + (size_t)row * DIMN))[t];

    __shared__ float red[8];
    float s = xv.x + xv.y + xv.z + xv.w;
    #pragma unroll
    for (int o = 16; o; o >>= 1) s += __shfl_xor_sync(0xffffffffu, s, o);
    if ((t & 31) == 0) red[t >> 5] = s;
    __syncthreads();
    float mean = 0.f;
    #pragma unroll
    for (int i = 0; i < 8; i++) mean += red[i];
    mean *= (1.0f / DIMN);
    __syncthreads();
    float d0 = xv.x - mean, d1 = xv.y - mean, d2 = xv.z - mean, d3 = xv.w - mean;
    float vs = d0*d0 + d1*d1 + d2*d2 + d3*d3;
    #pragma unroll
    for (int o = 16; o; o >>= 1) vs += __shfl_xor_sync(0xffffffffu, vs, o);
    if ((t & 31) == 0) red[t >> 5] = vs;
    __syncthreads();
    float var = 0.f;
    #pragma unroll
    for (int i = 0; i < 8; i++) var += red[i];
    var *= (1.0f / DIMN);
    const float inv = rsqrtf(var + 1e-5f);

    float4 wv = ((const float4*)w)[t];
    __nv_bfloat16* dst = g_xn + (size_t)row * DIMN + t * 4;
    *(__nv_bfloat162*)(dst)     = __floats2bfloat162_rn(d0*inv*wv.x, d1*inv*wv.y);
    *(__nv_bfloat162*)(dst + 2) = __floats2bfloat162_rn(d2*inv*wv.z, d3*inv*wv.w);
}

// ---------------- bf16 tensor-core GEMM:  C[m,n] = sum_k A[m,k]*B[n,k] ----------------
// MODE 0: plain fp32 out (+optional resid).  MODE 1: geglu epilogue on interleaved cols.
#define GBM 128
#define GBN 128
#define GBK 32
#define GLDA 40
#define ABYTES (GBM * GLDA * 2)

__device__ __forceinline__ void cpa16(uint32_t s, const void* g) {
    asm volatile("cp.async.cg.shared.global [%0], [%1], 16;\n" :: "r"(s), "l"(g));
}
__device__ __forceinline__ void ldsm4(uint32_t &r0, uint32_t &r1, uint32_t &r2, uint32_t &r3, uint32_t a) {
    asm volatile("ldmatrix.sync.aligned.m8n8.x4.shared.b16 {%0,%1,%2,%3}, [%4];"
                 : "=r"(r0), "=r"(r1), "=r"(r2), "=r"(r3) : "r"(a));
}
__device__ __forceinline__ void mma16816(float c[4], uint32_t a0, uint32_t a1, uint32_t a2, uint32_t a3,
                                         uint32_t b0, uint32_t b1) {
    asm volatile("mma.sync.aligned.m16n8k16.row.col.f32.bf16.bf16.f32 "
                 "{%0,%1,%2,%3}, {%4,%5,%6,%7}, {%8,%9}, {%0,%1,%2,%3};"
                 : "+f"(c[0]), "+f"(c[1]), "+f"(c[2]), "+f"(c[3])
                 : "r"(a0), "r"(a1), "r"(a2), "r"(a3), "r"(b0), "r"(b1));
}
__device__ __forceinline__ float gelu_exact(float x) {
    return 0.5f * x * (1.0f + erff(x * 0.70710678118654752f));
}

template<int MODE>
__global__ __launch_bounds__(256) void gemm_bf16(const __nv_bfloat16* __restrict__ A,
                                                 const __nv_bfloat16* __restrict__ B,
                                                 const float* __restrict__ resid,
                                                 float* __restrict__ Cf,
                                                 int M, int N, int K)
{
    __shared__ __align__(16) __nv_bfloat16 As[2][GBM * GLDA];
    __shared__ __align__(16) __nv_bfloat16 Bs[2][GBM * GLDA];

    const int tid  = threadIdx.x;
    const int lane = tid & 31;
    const int wid  = tid >> 5;
    const int wm   = wid >> 2;      // 0..1  (64 rows each)
    const int wn   = wid & 3;       // 0..3  (32 cols each)
    const int bm   = blockIdx.y * GBM;
    const int bn   = blockIdx.x * GBN;

    const uint32_t sA = (uint32_t)__cvta_generic_to_shared(&As[0][0]);
    const uint32_t sB = (uint32_t)__cvta_generic_to_shared(&Bs[0][0]);

    float acc[4][4][4];
    #pragma unroll
    for (int i = 0; i < 4; i++)
        #pragma unroll
        for (int j = 0; j < 4; j++)
            #pragma unroll
            for (int k = 0; k < 4; k++) acc[i][j][k] = 0.f;

    const int KT = K / GBK;
    const int lrow = tid >> 2, lcol8 = (tid & 3) * 8;

    auto load_tile = [&](int kt, int s) {
        const int k0 = kt * GBK;
        #pragma unroll
        for (int i = 0; i < 2; i++) {
            int row = lrow + i * 64;
            uint32_t so = (uint32_t)((row * GLDA + lcol8) * 2);
            cpa16(sA + s * ABYTES + so, A + (size_t)(bm + row) * K + k0 + lcol8);
            cpa16(sB + s * ABYTES + so, B + (size_t)(bn + row) * K + k0 + lcol8);
        }
        asm volatile("cp.async.commit_group;");
    };

    load_tile(0, 0);
    for (int kt = 0; kt < KT; kt++) {
        if (kt + 1 < KT) {
            load_tile(kt + 1, (kt + 1) & 1);
            asm volatile("cp.async.wait_group 1;");
        } else {
            asm volatile("cp.async.wait_group 0;");
        }
        __syncthreads();

        const uint32_t sAb = sA + (kt & 1) * ABYTES;
        const uint32_t sBb = sB + (kt & 1) * ABYTES;
        #pragma unroll
        for (int ks = 0; ks < 2; ks++) {
            uint32_t a[4][4], bf[4][2];
            #pragma unroll
            for (int mt = 0; mt < 4; mt++) {
                uint32_t ad = sAb + (uint32_t)(((wm*64 + mt*16 + (lane & 15)) * GLDA + ks*16 + (lane >> 4)*8) * 2);
                ldsm4(a[mt][0], a[mt][1], a[mt][2], a[mt][3], ad);
            }
            #pragma unroll
            for (int np = 0; np < 2; np++) {
                uint32_t m0, m1, m2, m3;
                uint32_t bd = sBb + (uint32_t)(((wn*32 + np*16 + (lane & 15)) * GLDA + ks*16 + (lane >> 4)*8) * 2);
                ldsm4(m0, m1, m2, m3, bd);
                bf[np*2 + 0][0] = m0; bf[np*2 + 0][1] = m2;
                bf[np*2 + 1][0] = m1; bf[np*2 + 1][1] = m3;
            }
            #pragma unroll
            for (int mt = 0; mt < 4; mt++)
                #pragma unroll
                for (int nt = 0; nt < 4; nt++)
                    mma16816(acc[mt][nt], a[mt][0], a[mt][1], a[mt][2], a[mt][3],
                             bf[nt][0], bf[nt][1]);
        }
        __syncthreads();
    }

    // ---- epilogue ----
    #pragma unroll
    for (int mt = 0; mt < 4; mt++) {
        const int r0 = bm + wm*64 + mt*16 + (lane >> 2);
        #pragma unroll
        for (int nt = 0; nt < 4; nt++) {
            const int col = bn + wn*32 + nt*8 + (lane & 3)*2;
            float c0 = acc[mt][nt][0], c1 = acc[mt][nt][1];
            float c2 = acc[mt][nt][2], c3 = acc[mt][nt][3];
            if (MODE == 0) {
                float2 v0 = make_float2(c0, c1);
                float2 v1 = make_float2(c2, c3);
                if (resid) {
                    float2 q0 = *(const float2*)(resid + (size_t)r0 * N + col);
                    float2 q1 = *(const float2*)(resid + (size_t)(r0+8) * N + col);
                    v0.x += q0.x; v0.y += q0.y; v1.x += q1.x; v1.y += q1.y;
                }
                *(float2*)(Cf + (size_t)r0 * N + col)     = v0;
                *(float2*)(Cf + (size_t)(r0+8) * N + col) = v1;
            } else {
                const int e = col >> 1;             // 0..2047
                float g0 = c0 * gelu_exact(c1);
                float g1 = c2 * gelu_exact(c3);
                if (e < 1024) {
                    g_go[(size_t)r0 * OUTC + e]     = __float2bfloat16(g0);
                    g_go[(size_t)(r0+8) * OUTC + e] = __float2bfloat16(g1);
                } else {
                    g_v[(size_t)r0 * DIMN + e - 1024]     = g0;
                    g_v[(size_t)(r0+8) * DIMN + e - 1024] = g1;
                }
            }
        }
    }
}

// ---------------- Attention (flash-style, causal + softplus(pbm)*(j-i) bias) ----------------
#define BQ  64
#define BKT 32
__global__ __launch_bounds__(256) void attn_kernel(const float* __restrict__ pbm_ptr)
{
    const int qb = blockIdx.x;
    const int bh = blockIdx.y;
    const int b  = bh >> 3, hd = bh & 7;
    const int q0 = qb * BQ;
    float pbm = *pbm_ptr;
    const float sp = (pbm > 20.f) ? pbm : log1pf(expf(pbm));
    const float scale = 0.25f;

    __shared__ __align__(16) float Qs[BQ][DQK];
    __shared__ __align__(16) float Ks[BKT][DQK];
    __shared__ __align__(16) float Vs[BKT][DV];
    __shared__ float Ps[BQ][BKT];

    const int tid  = threadIdx.x;
    const int warp = tid >> 5, lane = tid & 31;
    const size_t base = (size_t)b * SEQ;

    {
        int r = tid >> 2, c4 = (tid & 3) * 4;
        float4 qv = *(const float4*)(g_qk + (base + q0 + r) * QKW + hd*DQK + c4);
        Qs[r][c4] = qv.x; Qs[r][c4+1] = qv.y; Qs[r][c4+2] = qv.z; Qs[r][c4+3] = qv.w;
    }

    float acc[8][4];
    float mrow[8], lrow[8];
    #pragma unroll
    for (int i = 0; i < 8; i++) {
        mrow[i] = -INFINITY; lrow[i] = 0.f;
        acc[i][0] = acc[i][1] = acc[i][2] = acc[i][3] = 0.f;
    }

    const int ktmax = (q0 + BQ - 1) / BKT;
    __syncthreads();

    for (int kt = 0; kt <= ktmax; kt++) {
        const int k0 = kt * BKT;
        if (tid < 128) {
            int r = tid >> 2, c4 = (tid & 3) * 4;
            float4 kv = *(const float4*)(g_qk + (base + k0 + r) * QKW + 128 + hd*DQK + c4);
            Ks[r][c4] = kv.x; Ks[r][c4+1] = kv.y; Ks[r][c4+2] = kv.z; Ks[r][c4+3] = kv.w;
        }
        #pragma unroll
        for (int i = 0; i < 4; i++) {
            int li = tid + i * 256;
            int r  = li >> 5;
            int c4 = (li & 31) * 4;
            float4 vv = *(const float4*)(g_v + (base + k0 + r) * DIMN + hd*DV + c4);
            Vs[r][c4] = vv.x; Vs[r][c4+1] = vv.y; Vs[r][c4+2] = vv.z; Vs[r][c4+3] = vv.w;
        }
        __syncthreads();

        #pragma unroll
        for (int i = 0; i < 8; i++) {
            int e = tid + i * 256;
            int q = e >> 5, j = e & 31;
            const float* qv = Qs[q];
            const float* kv = Ks[j];
            float s = 0.f;
            #pragma unroll
            for (int d = 0; d < DQK; d++) s = fmaf(qv[d], kv[d], s);
            int qi = q0 + q, kj = k0 + j;
            s = s * scale + ((kj <= qi) ? sp * (float)(kj - qi) : -INFINITY);
            Ps[q][j] = s;
        }
        __syncthreads();

        #pragma unroll
        for (int i = 0; i < 8; i++) {
            int q = warp * 8 + i;
            float s = Ps[q][lane];
            float m = s;
            #pragma unroll
            for (int o = 16; o; o >>= 1) m = fmaxf(m, __shfl_xor_sync(0xffffffffu, m, o));
            float mn = fmaxf(mrow[i], m);
            float p  = __expf(s - mn);
            float ps = p;
            #pragma unroll
            for (int o = 16; o; o >>= 1) ps += __shfl_xor_sync(0xffffffffu, ps, o);
            float alpha = __expf(mrow[i] - mn);
            lrow[i] = lrow[i] * alpha + ps;
            mrow[i] = mn;
            Ps[q][lane] = p;
            #pragma unroll
            for (int d = 0; d < 4; d++) acc[i][d] *= alpha;
        }
        __syncwarp();

        #pragma unroll
        for (int i = 0; i < 8; i++) {
            int q = warp * 8 + i;
            #pragma unroll
            for (int j = 0; j < BKT; j++) {
                float p = Ps[q][j];
                float4 vv = *(const float4*)&Vs[j][lane * 4];
                acc[i][0] = fmaf(p, vv.x, acc[i][0]);
                acc[i][1] = fmaf(p, vv.y, acc[i][1]);
                acc[i][2] = fmaf(p, vv.z, acc[i][2]);
                acc[i][3] = fmaf(p, vv.w, acc[i][3]);
            }
        }
        __syncthreads();
    }

    #pragma unroll
    for (int i = 0; i < 8; i++) {
        int q = warp * 8 + i;
        float inv = 1.0f / lrow[i];
        __nv_bfloat16* dst = g_go + (base + q0 + q) * OUTC + 1024 + hd*DV + lane*4;
        *(__nv_bfloat162*)(dst)     = __floats2bfloat162_rn(acc[i][0]*inv, acc[i][1]*inv);
        *(__nv_bfloat162*)(dst + 2) = __floats2bfloat162_rn(acc[i][2]*inv, acc[i][3]*inv);
    }
}

// ---------------- Launch ----------------
extern "C" void kernel_launch(void* const* d_in, const int* in_sizes, int n_in,
                              void* d_out, int out_size)
{
    const float* x       = (const float*)d_in[0];
    const float* norm_w  = (const float*)d_in[1];
    const float* expand  = (const float*)d_in[2];
    const float* project = (const float*)d_in[3];
    const float* pbm     = (const float*)d_in[4];
    float* out = (float*)d_out;

    __nv_bfloat16 *p_xn, *p_eb, *p_pb, *p_go;
    float *p_qk;
    cudaGetSymbolAddress((void**)&p_xn, g_xn);
    cudaGetSymbolAddress((void**)&p_eb, g_eb);
    cudaGetSymbolAddress((void**)&p_pb, g_pb);
    cudaGetSymbolAddress((void**)&p_go, g_go);
    cudaGetSymbolAddress((void**)&p_qk, g_qk);

    conv_expand <<<ENROW, 256>>>(expand);
    conv_project<<<(DIMN * OUTC) / 1024, 256>>>(project);
    ln_kernel   <<<ROWS, 256>>>(x, norm_w);

    // geglu GEMM: 16384 x 4096 x 1024, fused gelu epilogue
    {
        dim3 grid(GEGN / GBN, ROWS / GBM);
        gemm_bf16<1><<<grid, 256>>>(p_xn, p_eb, nullptr, nullptr, ROWS, GEGN, DIMN);
    }
    // q/k GEMM: 16384 x 256 x 1024
    {
        dim3 grid(QKW / GBN, ROWS / GBM);
        gemm_bf16<0><<<grid, 256>>>(p_xn, p_eb + (size_t)GEGN * DIMN, nullptr, p_qk, ROWS, QKW, DIMN);
    }
    // attention
    {
        dim3 grid(SEQ / BQ, BATCH * HEADS);
        attn_kernel<<<grid, 256>>>(pbm);
    }
    // output GEMM: 16384 x 1024 x 2048 (+residual)
    {
        dim3 grid(DIMN / GBN, ROWS / GBM);
        gemm_bf16<0><<<grid, 256>>>(p_go, p_pb, x, out, ROWS, DIMN, OUTC);
    }
}

// round 4
// speedup vs baseline: 4.3338x; 1.2215x over previous
#include <cuda_runtime.h>
#include <cuda_bf16.h>
#include <math.h>
#include <stdint.h>

// ---------------- Problem constants ----------------
#define DIMN   1024
#define QKW    256
#define HEADS  8
#define DQK    16
#define DV     128
#define BATCH  16
#define SEQ    1024
#define ROWS   (BATCH*SEQ)     // 16384
#define ENROW  4352
#define GEGN   4096
#define OUTC   2048

// ---------------- Scratch ----------------
__device__ __nv_bfloat16 g_xn[(size_t)ROWS * DIMN];
__device__ __nv_bfloat16 g_eb[(size_t)ENROW * DIMN];
__device__ __nv_bfloat16 g_pb[(size_t)DIMN * OUTC];
__device__ float         g_qk[(size_t)ROWS * QKW];
__device__ __nv_bfloat16 g_v [(size_t)ROWS * DIMN];     // bf16 now
__device__ __nv_bfloat16 g_go[(size_t)ROWS * OUTC];

// ---------------- Weight conversion ----------------
__global__ __launch_bounds__(256) void conv_expand(const float* __restrict__ src)
{
    int i  = blockIdx.x * 256 + threadIdx.x;
    int r  = i >> 8;
    int c4 = (i & 255) * 4;
    int srow = (r < GEGN) ? ((r & 1) ? 2304 + (r >> 1) : 256 + (r >> 1)) : (r - GEGN);
    float4 v = *(const float4*)(src + (size_t)srow * DIMN + c4);
    __nv_bfloat16* dst = g_eb + (size_t)r * DIMN + c4;
    *(__nv_bfloat162*)(dst)     = __floats2bfloat162_rn(v.x, v.y);
    *(__nv_bfloat162*)(dst + 2) = __floats2bfloat162_rn(v.z, v.w);
}
__global__ __launch_bounds__(256) void conv_project(const float* __restrict__ src)
{
    int i  = blockIdx.x * 256 + threadIdx.x;
    float4 v = *(const float4*)(src + (size_t)i * 4);
    __nv_bfloat16* dst = g_pb + (size_t)i * 4;
    *(__nv_bfloat162*)(dst)     = __floats2bfloat162_rn(v.x, v.y);
    *(__nv_bfloat162*)(dst + 2) = __floats2bfloat162_rn(v.z, v.w);
}

// ---------------- LayerNorm -> bf16 ----------------
__global__ __launch_bounds__(256) void ln_kernel(const float* __restrict__ x,
                                                 const float* __restrict__ w)
{
    const int row = blockIdx.x;
    const int t   = threadIdx.x;
    float4 xv = ((const float4*)(x + (size_t)row * DIMN))[t];

    __shared__ float red[8];
    float s = xv.x + xv.y + xv.z + xv.w;
    #pragma unroll
    for (int o = 16; o; o >>= 1) s += __shfl_xor_sync(0xffffffffu, s, o);
    if ((t & 31) == 0) red[t >> 5] = s;
    __syncthreads();
    float mean = 0.f;
    #pragma unroll
    for (int i = 0; i < 8; i++) mean += red[i];
    mean *= (1.0f / DIMN);
    __syncthreads();
    float d0 = xv.x - mean, d1 = xv.y - mean, d2 = xv.z - mean, d3 = xv.w - mean;
    float vs = d0*d0 + d1*d1 + d2*d2 + d3*d3;
    #pragma unroll
    for (int o = 16; o; o >>= 1) vs += __shfl_xor_sync(0xffffffffu, vs, o);
    if ((t & 31) == 0) red[t >> 5] = vs;
    __syncthreads();
    float var = 0.f;
    #pragma unroll
    for (int i = 0; i < 8; i++) var += red[i];
    var *= (1.0f / DIMN);
    const float inv = rsqrtf(var + 1e-5f);

    float4 wv = ((const float4*)w)[t];
    __nv_bfloat16* dst = g_xn + (size_t)row * DIMN + t * 4;
    *(__nv_bfloat162*)(dst)     = __floats2bfloat162_rn(d0*inv*wv.x, d1*inv*wv.y);
    *(__nv_bfloat162*)(dst + 2) = __floats2bfloat162_rn(d2*inv*wv.z, d3*inv*wv.w);
}

// ---------------- PTX helpers ----------------
__device__ __forceinline__ void cpa16(uint32_t s, const void* g) {
    asm volatile("cp.async.cg.shared.global [%0], [%1], 16;\n" :: "r"(s), "l"(g));
}
__device__ __forceinline__ void ldsm4(uint32_t &r0, uint32_t &r1, uint32_t &r2, uint32_t &r3, uint32_t a) {
    asm volatile("ldmatrix.sync.aligned.m8n8.x4.shared.b16 {%0,%1,%2,%3}, [%4];"
                 : "=r"(r0), "=r"(r1), "=r"(r2), "=r"(r3) : "r"(a));
}
__device__ __forceinline__ void ldsm4t(uint32_t &r0, uint32_t &r1, uint32_t &r2, uint32_t &r3, uint32_t a) {
    asm volatile("ldmatrix.sync.aligned.m8n8.x4.trans.shared.b16 {%0,%1,%2,%3}, [%4];"
                 : "=r"(r0), "=r"(r1), "=r"(r2), "=r"(r3) : "r"(a));
}
__device__ __forceinline__ void mma16816(float c[4], uint32_t a0, uint32_t a1, uint32_t a2, uint32_t a3,
                                         uint32_t b0, uint32_t b1) {
    asm volatile("mma.sync.aligned.m16n8k16.row.col.f32.bf16.bf16.f32 "
                 "{%0,%1,%2,%3}, {%4,%5,%6,%7}, {%8,%9}, {%0,%1,%2,%3};"
                 : "+f"(c[0]), "+f"(c[1]), "+f"(c[2]), "+f"(c[3])
                 : "r"(a0), "r"(a1), "r"(a2), "r"(a3), "r"(b0), "r"(b1));
}
__device__ __forceinline__ float gelu_exact(float x) {
    return 0.5f * x * (1.0f + erff(x * 0.70710678118654752f));
}

// ---------------- bf16 GEMM, 3-stage cp.async pipeline ----------------
#define GBM 128
#define GBN 128
#define GBK 32
#define GLDA 40
#define ABYTES (GBM * GLDA * 2)   // 10240
#define NSTAGE 3

template<int MODE>
__global__ __launch_bounds__(256) void gemm_bf16(const __nv_bfloat16* __restrict__ A,
                                                 const __nv_bfloat16* __restrict__ B,
                                                 const float* __restrict__ resid,
                                                 float* __restrict__ Cf,
                                                 int M, int N, int K)
{
    extern __shared__ __align__(16) char dynsmem[];
    __nv_bfloat16* Asm = (__nv_bfloat16*)dynsmem;
    __nv_bfloat16* Bsm = Asm + NSTAGE * GBM * GLDA;

    const int tid  = threadIdx.x;
    const int lane = tid & 31;
    const int wid  = tid >> 5;
    const int wm   = wid >> 2;
    const int wn   = wid & 3;
    const int bm   = blockIdx.y * GBM;
    const int bn   = blockIdx.x * GBN;

    const uint32_t sA = (uint32_t)__cvta_generic_to_shared(Asm);
    const uint32_t sB = (uint32_t)__cvta_generic_to_shared(Bsm);

    float acc[4][4][4];
    #pragma unroll
    for (int i = 0; i < 4; i++)
        #pragma unroll
        for (int j = 0; j < 4; j++)
            #pragma unroll
            for (int k = 0; k < 4; k++) acc[i][j][k] = 0.f;

    const int KT = K / GBK;
    const int lrow = tid >> 2, lcol8 = (tid & 3) * 8;

    auto load_tile = [&](int kt, int s) {
        const int k0 = kt * GBK;
        #pragma unroll
        for (int i = 0; i < 2; i++) {
            int row = lrow + i * 64;
            uint32_t so = (uint32_t)((row * GLDA + lcol8) * 2) + (uint32_t)(s * ABYTES);
            cpa16(sA + so, A + (size_t)(bm + row) * K + k0 + lcol8);
            cpa16(sB + so, B + (size_t)(bn + row) * K + k0 + lcol8);
        }
        asm volatile("cp.async.commit_group;");
    };

    load_tile(0, 0);
    load_tile(1, 1);

    for (int kt = 0; kt < KT; kt++) {
        asm volatile("cp.async.wait_group 1;");
        __syncthreads();
        if (kt + 2 < KT) load_tile(kt + 2, (kt + 2) % NSTAGE);
        else asm volatile("cp.async.commit_group;");

        const uint32_t sAb = sA + (kt % NSTAGE) * ABYTES;
        const uint32_t sBb = sB + (kt % NSTAGE) * ABYTES;
        #pragma unroll
        for (int ks = 0; ks < 2; ks++) {
            uint32_t a[4][4], bf[4][2];
            #pragma unroll
            for (int mt = 0; mt < 4; mt++) {
                uint32_t ad = sAb + (uint32_t)(((wm*64 + mt*16 + (lane & 15)) * GLDA + ks*16 + (lane >> 4)*8) * 2);
                ldsm4(a[mt][0], a[mt][1], a[mt][2], a[mt][3], ad);
            }
            #pragma unroll
            for (int np = 0; np < 2; np++) {
                uint32_t m0, m1, m2, m3;
                uint32_t bd = sBb + (uint32_t)(((wn*32 + np*16 + (lane & 15)) * GLDA + ks*16 + (lane >> 4)*8) * 2);
                ldsm4(m0, m1, m2, m3, bd);
                bf[np*2 + 0][0] = m0; bf[np*2 + 0][1] = m2;
                bf[np*2 + 1][0] = m1; bf[np*2 + 1][1] = m3;
            }
            #pragma unroll
            for (int mt = 0; mt < 4; mt++)
                #pragma unroll
                for (int nt = 0; nt < 4; nt++)
                    mma16816(acc[mt][nt], a[mt][0], a[mt][1], a[mt][2], a[mt][3],
                             bf[nt][0], bf[nt][1]);
        }
    }

    #pragma unroll
    for (int mt = 0; mt < 4; mt++) {
        const int r0 = bm + wm*64 + mt*16 + (lane >> 2);
        #pragma unroll
        for (int nt = 0; nt < 4; nt++) {
            const int col = bn + wn*32 + nt*8 + (lane & 3)*2;
            float c0 = acc[mt][nt][0], c1 = acc[mt][nt][1];
            float c2 = acc[mt][nt][2], c3 = acc[mt][nt][3];
            if (MODE == 0) {
                float2 v0 = make_float2(c0, c1);
                float2 v1 = make_float2(c2, c3);
                if (resid) {
                    float2 q0 = *(const float2*)(resid + (size_t)r0 * N + col);
                    float2 q1 = *(const float2*)(resid + (size_t)(r0+8) * N + col);
                    v0.x += q0.x; v0.y += q0.y; v1.x += q1.x; v1.y += q1.y;
                }
                *(float2*)(Cf + (size_t)r0 * N + col)     = v0;
                *(float2*)(Cf + (size_t)(r0+8) * N + col) = v1;
            } else {
                const int e = col >> 1;
                float g0 = c0 * gelu_exact(c1);
                float g1 = c2 * gelu_exact(c3);
                if (e < 1024) {
                    g_go[(size_t)r0 * OUTC + e]     = __float2bfloat16(g0);
                    g_go[(size_t)(r0+8) * OUTC + e] = __float2bfloat16(g1);
                } else {
                    g_v[(size_t)r0 * DIMN + e - 1024]     = __float2bfloat16(g0);
                    g_v[(size_t)(r0+8) * DIMN + e - 1024] = __float2bfloat16(g1);
                }
            }
        }
    }
}

// ---------------- Attention: SIMT scores/softmax + tensor-core P@V ----------------
#define BQ  64
#define BKT 32
#define VLD 136     // bf16 pitch for V tile (conflict-free ldsm.trans)
#define PLD 40      // bf16 pitch for P tile

__global__ __launch_bounds__(256) void attn_kernel(const float* __restrict__ pbm_ptr)
{
    const int qb = blockIdx.x;
    const int bh = blockIdx.y;
    const int b  = bh >> 3, hd = bh & 7;
    const int q0 = qb * BQ;
    float pbm = *pbm_ptr;
    const float sp = (pbm > 20.f) ? pbm : log1pf(expf(pbm));
    const float scale = 0.25f;

    __shared__ float Qs[BQ][DQK];                       // 4 KB
    __shared__ float Ks[BKT][17];                       // 2.1 KB (odd pitch: conflict-free)
    __shared__ __align__(16) __nv_bfloat16 Vs[BKT][VLD];// 8.5 KB
    __shared__ __align__(16) __nv_bfloat16 Psb[BQ][PLD];// 5 KB
    __shared__ float alpha_s[BQ];
    __shared__ float linv_s[BQ];

    const int tid  = threadIdx.x;
    const int warp = tid >> 5, lane = tid & 31;
    const int wm   = warp >> 1;         // 0..3 : 16 query rows
    const int wn   = warp & 1;          // 0..1 : 64 dv cols
    const size_t base = (size_t)b * SEQ;

    const uint32_t vbase = (uint32_t)__cvta_generic_to_shared(&Vs[0][0]);
    const uint32_t pbase = (uint32_t)__cvta_generic_to_shared(&Psb[0][0]);

    // Q tile (64x16 fp32)
    {
        int r = tid >> 2, c4 = (tid & 3) * 4;
        float4 qv = *(const float4*)(g_qk + (base + q0 + r) * QKW + hd*DQK + c4);
        Qs[r][c4] = qv.x; Qs[r][c4+1] = qv.y; Qs[r][c4+2] = qv.z; Qs[r][c4+3] = qv.w;
    }

    float acc[8][4];        // 16 q-rows x 64 dv per warp
    #pragma unroll
    for (int f = 0; f < 8; f++)
        acc[f][0] = acc[f][1] = acc[f][2] = acc[f][3] = 0.f;
    float mrow[8], lrow[8];
    #pragma unroll
    for (int i = 0; i < 8; i++) { mrow[i] = -INFINITY; lrow[i] = 0.f; }

    const int ktmax = (q0 + BQ - 1) / BKT;
    __syncthreads();

    for (int kt = 0; kt <= ktmax; kt++) {
        const int k0 = kt * BKT;
        // K tile (32x16 fp32)
        if (tid < 128) {
            int r = tid >> 2, c4 = (tid & 3) * 4;
            float4 kv = *(const float4*)(g_qk + (base + k0 + r) * QKW + 128 + hd*DQK + c4);
            Ks[r][c4] = kv.x; Ks[r][c4+1] = kv.y; Ks[r][c4+2] = kv.z; Ks[r][c4+3] = kv.w;
        }
        // V tile (32x128 bf16) via cp.async: 512 x 16B chunks
        #pragma unroll
        for (int t = 0; t < 2; t++) {
            int idx = tid + t * 256;
            int r = idx >> 4, c16 = idx & 15;
            cpa16(vbase + (uint32_t)(r * VLD * 2 + c16 * 16),
                  g_v + (base + k0 + r) * DIMN + hd*DV + c16*8);
        }
        asm volatile("cp.async.commit_group;");
        asm volatile("cp.async.wait_group 0;");
        __syncthreads();

        // softmax warp: rows warp*8 .. warp*8+7 ; lane = key index
        float kr[DQK];
        #pragma unroll
        for (int d = 0; d < DQK; d++) kr[d] = Ks[lane][d];
        const int kj = k0 + lane;

        #pragma unroll
        for (int i = 0; i < 8; i++) {
            const int row = warp * 8 + i;
            const int qi  = q0 + row;
            float s = 0.f;
            #pragma unroll
            for (int d = 0; d < DQK; d++) s = fmaf(Qs[row][d], kr[d], s);
            s = s * scale + ((kj <= qi) ? sp * (float)(kj - qi) : -INFINITY);
            float m = s;
            #pragma unroll
            for (int o = 16; o; o >>= 1) m = fmaxf(m, __shfl_xor_sync(0xffffffffu, m, o));
            float mn = fmaxf(mrow[i], m);
            float p  = __expf(s - mn);
            float ps = p;
            #pragma unroll
            for (int o = 16; o; o >>= 1) ps += __shfl_xor_sync(0xffffffffu, ps, o);
            float alpha = __expf(mrow[i] - mn);
            lrow[i] = lrow[i] * alpha + ps;
            mrow[i] = mn;
            Psb[row][lane] = __float2bfloat16(p);
            if (lane == 0) alpha_s[row] = alpha;
        }
        __syncthreads();

        // mma phase: O[16q x 64dv] += P[16q x 32k] @ V[32k x 64dv]
        {
            const int r = wm*16 + (lane >> 2);
            float a0 = alpha_s[r], a1 = alpha_s[r + 8];
            #pragma unroll
            for (int f = 0; f < 8; f++) {
                acc[f][0] *= a0; acc[f][1] *= a0;
                acc[f][2] *= a1; acc[f][3] *= a1;
            }
            #pragma unroll
            for (int ks = 0; ks < 2; ks++) {
                uint32_t a0r, a1r, a2r, a3r;
                uint32_t ad = pbase + (uint32_t)(((wm*16 + (lane & 15)) * PLD + ks*16 + (lane >> 4)*8) * 2);
                ldsm4(a0r, a1r, a2r, a3r, ad);
                #pragma unroll
                for (int g = 0; g < 4; g++) {
                    uint32_t b0, b1, b2, b3;
                    uint32_t bd = vbase + (uint32_t)(((ks*16 + (lane & 15)) * VLD + wn*64 + g*16 + (lane >> 4)*8) * 2);
                    ldsm4t(b0, b1, b2, b3, bd);
                    mma16816(acc[g*2 + 0], a0r, a1r, a2r, a3r, b0, b1);
                    mma16816(acc[g*2 + 1], a0r, a1r, a2r, a3r, b2, b3);
                }
            }
        }
        __syncthreads();
    }

    // final 1/l
    if (lane == 0) {
        #pragma unroll
        for (int i = 0; i < 8; i++) linv_s[warp*8 + i] = 1.0f / lrow[i];
    }
    __syncthreads();

    {
        const int r  = wm*16 + (lane >> 2);
        const float l0 = linv_s[r], l1 = linv_s[r + 8];
        #pragma unroll
        for (int f = 0; f < 8; f++) {
            int n = wn*64 + f*8 + (lane & 3)*2;
            __nv_bfloat16* d0 = g_go + (base + q0 + r) * OUTC + 1024 + hd*DV + n;
            __nv_bfloat16* d1 = g_go + (base + q0 + r + 8) * OUTC + 1024 + hd*DV + n;
            *(__nv_bfloat162*)d0 = __floats2bfloat162_rn(acc[f][0]*l0, acc[f][1]*l0);
            *(__nv_bfloat162*)d1 = __floats2bfloat162_rn(acc[f][2]*l1, acc[f][3]*l1);
        }
    }
}

// ---------------- Launch ----------------
extern "C" void kernel_launch(void* const* d_in, const int* in_sizes, int n_in,
                              void* d_out, int out_size)
{
    const float* x       = (const float*)d_in[0];
    const float* norm_w  = (const float*)d_in[1];
    const float* expand  = (const float*)d_in[2];
    const float* project = (const float*)d_in[3];
    const float* pbm     = (const float*)d_in[4];
    float* out = (float*)d_out;

    __nv_bfloat16 *p_xn, *p_eb, *p_pb, *p_go;
    float *p_qk;
    cudaGetSymbolAddress((void**)&p_xn, g_xn);
    cudaGetSymbolAddress((void**)&p_eb, g_eb);
    cudaGetSymbolAddress((void**)&p_pb, g_pb);
    cudaGetSymbolAddress((void**)&p_go, g_go);
    cudaGetSymbolAddress((void**)&p_qk, g_qk);

    const int shbytes = NSTAGE * ABYTES * 2;    // 61440
    cudaFuncSetAttribute(gemm_bf16<0>, cudaFuncAttributeMaxDynamicSharedMemorySize, shbytes);
    cudaFuncSetAttribute(gemm_bf16<1>, cudaFuncAttributeMaxDynamicSharedMemorySize, shbytes);

    conv_expand <<<ENROW, 256>>>(expand);
    conv_project<<<(DIMN * OUTC) / 1024, 256>>>(project);
    ln_kernel   <<<ROWS, 256>>>(x, norm_w);

    {   // geglu GEMM: 16384 x 4096 x 1024 (fused gelu epilogue)
        dim3 grid(GEGN / GBN, ROWS / GBM);
        gemm_bf16<1><<<grid, 256, shbytes>>>(p_xn, p_eb, nullptr, nullptr, ROWS, GEGN, DIMN);
    }
    {   // q/k GEMM: 16384 x 256 x 1024
        dim3 grid(QKW / GBN, ROWS / GBM);
        gemm_bf16<0><<<grid, 256, shbytes>>>(p_xn, p_eb + (size_t)GEGN * DIMN, nullptr, p_qk, ROWS, QKW, DIMN);
    }
    {   // attention
        dim3 grid(SEQ / BQ, BATCH * HEADS);
        attn_kernel<<<grid, 256>>>(pbm);
    }
    {   // output GEMM: 16384 x 1024 x 2048 (+residual)
        dim3 grid(DIMN / GBN, ROWS / GBM);
        gemm_bf16<0><<<grid, 256, shbytes>>>(p_go, p_pb, x, out, ROWS, DIMN, OUTC);
    }
}